// round 7
// baseline (speedup 1.0000x reference)
#include <cuda_runtime.h>
#include <cstdint>

// Problem constants
#define B 32
#define L 6
#define R 8
#define H 64
#define NTRAJ 262144              // R^L
#define F4_PER_B 393216           // NTRAJ * L / 4
#define TRAJ_PER_BLK 4096
#define F4_PER_BLK   6144         // TRAJ_PER_BLK * 6 / 4

// ---------------------------------------------------------------------------
// Single fused kernel.
// Phase 1 (per-block, redundant per batch): compute the 48 q0[b][l][r] values.
//   512 threads = 8 items x 64 hidden lanes; 6 rounds cover 48 items.
//   W2 staged coalesced into shared with 65-float pitch (conflict-free reads).
// Phase 2: expansion out[b][n][l] = q0[b][l][(n>>3l)&7], proven R4 STG body:
//   6144 coalesced float4s per block, chunk-constant digits l>=3.
// ---------------------------------------------------------------------------
__global__ void __launch_bounds__(512) zdec_fused_kernel(
    const float* __restrict__ phi,   // (B, L)
    const float* __restrict__ rp,    // (L, R, 1)
    const float* __restrict__ W1,    // (H, 2)
    const float* __restrict__ b1,
    const float* __restrict__ W2,    // (H, H)
    const float* __restrict__ b2,
    const float* __restrict__ W3,    // (OUT, H) — row 0 only
    const float* __restrict__ b3,
    float* __restrict__ out)
{
    __shared__ float sW2[H * 65];            // 16.25 KB
    __shared__ float sh1[8][H];
    __shared__ float sred[8][2];
    __shared__ float sq[L * R];

    const int tid = threadIdx.x;
    const int b   = blockIdx.y;

    // ---- Phase 1: MLP for this batch's 48 (l,r) items -------------------
    const int item = tid >> 6;               // 0..7
    const int j    = tid & 63;               // hidden lane

    // coalesced W2 stage
#pragma unroll
    for (int t = tid; t < H * H; t += 512) {
        const int g = t >> 6, k = t & 63;
        sW2[g * 65 + k] = W2[t];
    }

    const float2 w1  = reinterpret_cast<const float2*>(W1)[j];
    const float  b1j = b1[j];
    const float  b2j = b2[j];
    const float  w3j = W3[j];
    const float  b30 = b3[0];
    __syncthreads();

#pragma unroll
    for (int rnd = 0; rnd < 6; rnd++) {
        const int lr = rnd * 8 + item;       // 0..47
        const int l  = lr >> 3;
        const float x = rp[lr];
        const float p = phi[b * L + l];

        sh1[item][j] = fmaxf(fmaf(w1.x, x, fmaf(w1.y, p, b1j)), 0.0f);
        __syncthreads();

        float acc = b2j;
#pragma unroll
        for (int k = 0; k < H; k++)
            acc = fmaf(sW2[j * 65 + k], sh1[item][k], acc);

        float q = w3j * fmaxf(acc, 0.0f);
#pragma unroll
        for (int off = 16; off > 0; off >>= 1)
            q += __shfl_xor_sync(0xffffffffu, q, off);
        if ((j & 31) == 0) sred[item][j >> 5] = q;
        __syncthreads();
        if (j == 0)
            sq[lr] = sred[item][0] + sred[item][1] + b30;
    }
    __syncthreads();

    // ---- Phase 2: expansion (R4 proven body) ----------------------------
    const int n_blk = blockIdx.x * TRAJ_PER_BLK;
    float4* op = reinterpret_cast<float4*>(out)
               + (size_t)b * F4_PER_B + (size_t)blockIdx.x * F4_PER_BLK;

#pragma unroll
    for (int it = 0; it < F4_PER_BLK / 512; it++) {
        const int jl_blk = it * 512 + tid;
        const int ch  = jl_blk / 768;
        const int jl  = jl_blk - ch * 768;             // 0..767 within chunk
        const int nc  = n_blk + ch * 512;
        const float c3 = sq[24 + ((nc >> 9)  & 7)];
        const float c4 = sq[32 + ((nc >> 12) & 7)];
        const float c5 = sq[40 + ((nc >> 15) & 7)];

        const int n   = (2 * jl) / 3;                  // local traj 0..511
        const int pat = jl % 3;
        const int d0 = n & 7;
        const int d1 = (n >> 3) & 7;
        const int d2 = (n >> 6) & 7;

        float4 v;
        if (pat == 0) {
            v.x = sq[d0];  v.y = sq[8 + d1];  v.z = sq[16 + d2];  v.w = c3;
        } else if (pat == 1) {
            v.x = c4;  v.y = c5;  v.z = sq[d0 + 1];  v.w = sq[8 + d1];
        } else {
            v.x = sq[16 + d2];  v.y = c3;  v.z = c4;  v.w = c5;
        }
        __stcs(op + jl_blk, v);
    }
}

// ---------------------------------------------------------------------------
extern "C" void kernel_launch(void* const* d_in, const int* in_sizes, int n_in,
                              void* d_out, int out_size)
{
    const float* phi = (const float*)d_in[0];
    const float* rp  = (const float*)d_in[1];
    const float* W1  = (const float*)d_in[2];
    const float* b1  = (const float*)d_in[3];
    const float* W2  = (const float*)d_in[4];
    const float* b2  = (const float*)d_in[5];
    const float* W3  = (const float*)d_in[6];
    const float* b3  = (const float*)d_in[7];
    float* out = (float*)d_out;

    dim3 grid(NTRAJ / TRAJ_PER_BLK, B);                // (64, 32)
    zdec_fused_kernel<<<grid, 512>>>(phi, rp, W1, b1, W2, b2, W3, b3, out);
}

// round 8
// speedup vs baseline: 2.7489x; 2.7489x over previous
#include <cuda_runtime.h>
#include <cstdint>

// Problem constants
#define B 32
#define L 6
#define R 8
#define H 64
#define NTRAJ 262144              // R^L
#define F4_PER_B 393216           // NTRAJ * L / 4
#define TRAJ_PER_BLK 4096
#define F4_PER_BLK   6144         // TRAJ_PER_BLK * 6 / 4
#define ITEMS_PER_MLP_BLK 4

// Scratch for the 1536 MLP outputs q0[b][l][r]
__device__ float g_q0[B * L * R];

// ---------------------------------------------------------------------------
// Kernel 1: tiny MLP, 4 items per 256-thread block (proven R4 version).
// ---------------------------------------------------------------------------
__global__ void __launch_bounds__(256) zdec_mlp_kernel(
    const float* __restrict__ phi, const float* __restrict__ rp,
    const float* __restrict__ W1,  const float* __restrict__ b1,
    const float* __restrict__ W2,  const float* __restrict__ b2,
    const float* __restrict__ W3,  const float* __restrict__ b3)
{
    __shared__ float sW2[H * 65];
    __shared__ float sh1[ITEMS_PER_MLP_BLK][H];
    __shared__ float sred[ITEMS_PER_MLP_BLK][2];

    const int tid  = threadIdx.x;
    const int item = tid >> 6;
    const int j    = tid & 63;

#pragma unroll
    for (int t = tid; t < H * H; t += 256) {
        const int g = t >> 6, k = t & 63;
        sW2[g * 65 + k] = W2[t];
    }

    const int ii = blockIdx.x * ITEMS_PER_MLP_BLK + item;
    const int b  = ii / (L * R);
    const int lr = ii % (L * R);
    const int l  = lr / R;

    const float  x  = rp[lr];
    const float  p  = phi[b * L + l];
    const float2 w1 = reinterpret_cast<const float2*>(W1)[j];

    sh1[item][j] = fmaxf(fmaf(w1.x, x, fmaf(w1.y, p, b1[j])), 0.0f);
    __syncthreads();

    float acc = b2[j];
#pragma unroll
    for (int k = 0; k < H; k++)
        acc = fmaf(sW2[j * 65 + k], sh1[item][k], acc);

    float q = W3[j] * fmaxf(acc, 0.0f);
#pragma unroll
    for (int off = 16; off > 0; off >>= 1)
        q += __shfl_xor_sync(0xffffffffu, q, off);
    if ((j & 31) == 0) sred[item][j >> 5] = q;
    __syncthreads();
    if (j == 0)
        g_q0[ii] = sred[item][0] + sred[item][1] + b3[0];
}

// ---------------------------------------------------------------------------
// Kernel 2: expansion (proven R4 STG body) + PDL grid-dependency sync.
// Blocks launch concurrently with the MLP kernel; they do their setup, then
// block at cudaGridDependencySynchronize() until the MLP grid completes
// (making g_q0 visible), then run the 30 µs store stream.
// ---------------------------------------------------------------------------
__global__ void __launch_bounds__(512) zdec_expand_kernel(float* __restrict__ out)
{
    __shared__ float sq[L * R];

    const int tid = threadIdx.x;
    const int b   = blockIdx.y;

    // Pre-dependency setup (overlaps with MLP kernel execution)
    const int n_blk = blockIdx.x * TRAJ_PER_BLK;
    float4* op = reinterpret_cast<float4*>(out)
               + (size_t)b * F4_PER_B + (size_t)blockIdx.x * F4_PER_BLK;

    // Wait for the MLP grid to finish; its writes to g_q0 are then visible.
    cudaGridDependencySynchronize();

    if (tid < L * R)
        sq[tid] = g_q0[b * (L * R) + tid];
    __syncthreads();

#pragma unroll
    for (int it = 0; it < F4_PER_BLK / 512; it++) {
        const int jl_blk = it * 512 + tid;
        const int ch  = jl_blk / 768;
        const int jl  = jl_blk - ch * 768;             // 0..767 within chunk
        const int nc  = n_blk + ch * 512;
        const float c3 = sq[24 + ((nc >> 9)  & 7)];
        const float c4 = sq[32 + ((nc >> 12) & 7)];
        const float c5 = sq[40 + ((nc >> 15) & 7)];

        const int n   = (2 * jl) / 3;                  // local traj 0..511
        const int pat = jl % 3;
        const int d0 = n & 7;
        const int d1 = (n >> 3) & 7;
        const int d2 = (n >> 6) & 7;

        float4 v;
        if (pat == 0) {
            v.x = sq[d0];  v.y = sq[8 + d1];  v.z = sq[16 + d2];  v.w = c3;
        } else if (pat == 1) {
            v.x = c4;  v.y = c5;  v.z = sq[d0 + 1];  v.w = sq[8 + d1];
        } else {
            v.x = sq[16 + d2];  v.y = c3;  v.z = c4;  v.w = c5;
        }
        __stcs(op + jl_blk, v);
    }
}

// ---------------------------------------------------------------------------
extern "C" void kernel_launch(void* const* d_in, const int* in_sizes, int n_in,
                              void* d_out, int out_size)
{
    const float* phi = (const float*)d_in[0];
    const float* rp  = (const float*)d_in[1];
    const float* W1  = (const float*)d_in[2];
    const float* b1  = (const float*)d_in[3];
    const float* W2  = (const float*)d_in[4];
    const float* b2  = (const float*)d_in[5];
    const float* W3  = (const float*)d_in[6];
    const float* b3  = (const float*)d_in[7];
    float* out = (float*)d_out;

    zdec_mlp_kernel<<<(B * L * R) / ITEMS_PER_MLP_BLK, 256>>>(
        phi, rp, W1, b1, W2, b2, W3, b3);

    // Secondary launch with programmatic dependent launch: its grid may be
    // dispatched while the MLP kernel runs; correctness is enforced by
    // cudaGridDependencySynchronize() inside the kernel.
    cudaLaunchConfig_t cfg = {};
    cfg.gridDim  = dim3(NTRAJ / TRAJ_PER_BLK, B);      // (64, 32)
    cfg.blockDim = dim3(512, 1, 1);
    cfg.dynamicSmemBytes = 0;
    cfg.stream = 0;

    cudaLaunchAttribute attr[1];
    attr[0].id = cudaLaunchAttributeProgrammaticStreamSerialization;
    attr[0].val.programmaticStreamSerializationAllowed = 1;
    cfg.attrs = attr;
    cfg.numAttrs = 1;

    cudaLaunchKernelEx(&cfg, zdec_expand_kernel, out);
}